// round 7
// baseline (speedup 1.0000x reference)
#include <cuda_runtime.h>
#include <cuda_bf16.h>
#include <cstdint>

// Problem constants (fixed by the dataset)
#define N_NODES 100000
#define N_EDGES 1600000
#define N_FEAT  128
#define HIDDEN  64
#define N_OUT   10
#define N_GRAPHS 64

#define SCAN_B 1024
#define N_SCAN_BLOCKS ((N_NODES + SCAN_B - 1) / SCAN_B)   // 98

// ---------------- device scratch (static, no allocation) ----------------
__device__ int    g_deg[N_NODES];          // degree incl. self loop
__device__ float  g_dis[N_NODES];          // rsqrt(deg)
__device__ int    g_rowptr[N_NODES + 1];   // CSR offsets (edges only)
__device__ int    g_cursor[N_NODES];       // fill cursors
__device__ int    g_scan_tmp[N_NODES];     // per-block exclusive scan
__device__ int    g_bsum[N_SCAN_BLOCKS];   // per-block totals from scan1
__device__ __align__(16) int2  g_csr_pack[N_EDGES];              // (src, norm-as-bits)
__device__ __align__(16) float g_tmpA[(size_t)N_NODES * HIDDEN]; // h @ W
__device__ __align__(16) float g_tmpB[(size_t)N_NODES * HIDDEN]; // aggregated h
__device__ float  g_pool_sums[N_GRAPHS * HIDDEN];
__device__ float  g_pool_cnt[N_GRAPHS];

// packed f32x2 fma: d = a*b + d (elementwise on 2 floats in a u64)
__device__ __forceinline__ void fma2(unsigned long long& d,
                                     unsigned long long a,
                                     unsigned long long b) {
    asm("fma.rn.f32x2 %0, %1, %2, %0;" : "+l"(d) : "l"(a), "l"(b));
}
__device__ __forceinline__ unsigned long long dup_f32(float v) {
    unsigned int u = __float_as_uint(v);
    return ((unsigned long long)u << 32) | u;
}

// ---------------- init: deg=1 (self loop), zero pool accumulators -------
__global__ void init_kernel() {
    int i = blockIdx.x * blockDim.x + threadIdx.x;
    if (i < N_NODES) g_deg[i] = 1;
    if (i < N_GRAPHS * HIDDEN) g_pool_sums[i] = 0.f;
    if (i < N_GRAPHS) g_pool_cnt[i] = 0.f;
}

// ---------------- degree histogram over targets (col) -------------------
__global__ void count_kernel(const int* __restrict__ ei) {
    int e = blockIdx.x * blockDim.x + threadIdx.x;
    if (e < N_EDGES) {
        int c = ei[e + N_EDGES];   // col / target
        atomicAdd(&g_deg[c], 1);
    }
}

// ---------------- exclusive scan of (deg-1) over 100K nodes + dis -------
__global__ void scan1_kernel() {
    __shared__ int s[SCAN_B];
    int tid = threadIdx.x;
    int i = blockIdx.x * SCAN_B + tid;
    int deg = (i < N_NODES) ? g_deg[i] : 1;
    if (i < N_NODES) g_dis[i] = rsqrtf((float)deg);
    int v = deg - 1;
    s[tid] = v;
    __syncthreads();
    #pragma unroll
    for (int off = 1; off < SCAN_B; off <<= 1) {
        int t = (tid >= off) ? s[tid - off] : 0;
        __syncthreads();
        s[tid] += t;
        __syncthreads();
    }
    if (i < N_NODES) g_scan_tmp[i] = s[tid] - v;   // exclusive
    if (tid == SCAN_B - 1) g_bsum[blockIdx.x] = s[tid];
}

// scan3: each block computes its offset by summing g_bsum[0..blockIdx-1]
// (98 ints from L2, serial in thread 0 — cheap, overlapped across blocks)
__global__ void scan3_kernel() {
    __shared__ int base;
    if (threadIdx.x == 0) {
        int run = 0;
        for (int b = 0; b < blockIdx.x; b++) run += g_bsum[b];
        base = run;
        if (blockIdx.x == 0) g_rowptr[N_NODES] = N_EDGES;
    }
    __syncthreads();
    int i = blockIdx.x * SCAN_B + threadIdx.x;
    if (i < N_NODES) {
        int v = g_scan_tmp[i] + base;
        g_rowptr[i] = v;
        g_cursor[i] = v;
    }
}

// ---------------- CSR fill with precomputed norm -------------------------
__global__ void fill_kernel(const int* __restrict__ ei) {
    int e = blockIdx.x * blockDim.x + threadIdx.x;
    if (e < N_EDGES) {
        int r = ei[e];
        int c = ei[e + N_EDGES];
        int pos = atomicAdd(&g_cursor[c], 1);
        float nr = g_dis[r] * g_dis[c];
        g_csr_pack[pos] = make_int2(r, __float_as_int(nr));
    }
}

// ---------------- SGEMM via packed f32x2 FMA -----------------------------
// C[M,64] = A[M,K] @ W[K,64].  A = x (sel==0) or g_tmpB (sel==1).
// 128x64 block tile, 256 threads.
// Microtile: 4 rows (ty=tid>>3, rows ty*4..+3, ty in 0..31)
//          x 8 cols (tx=tid&7,  cols tx*8..+7  -> u64s tx*4..+3 of 32/row)
// A tile stored pre-duplicated in smem as (a,a) u64; W pairs read natively.
template <int K>
__global__ __launch_bounds__(256)
void gemm_kernel(const float* __restrict__ x, const float* __restrict__ W,
                 int sel, int M) {
    constexpr int KC = 16;
    __shared__ __align__(16) float Ws[K * 64];                    // <=32KB
    __shared__ __align__(16) unsigned long long As[KC * 128];     // 16KB

    const float* __restrict__ A = (sel == 0) ? x : (const float*)g_tmpB;
    float* __restrict__ C = g_tmpA;

    const int tid = threadIdx.x;
    const int tx = tid & 7;     // col group: cols tx*8 .. tx*8+7 (max 63)
    const int ty = tid >> 3;    // row group: rows ty*4 .. ty*4+3 (max 127)
    const int row0 = blockIdx.x * 128;

    for (int i = tid; i < K * 16; i += 256)
        *(float4*)(Ws + i * 4) = *(const float4*)(W + i * 4);

    unsigned long long acc[4][4];
    #pragma unroll
    for (int r = 0; r < 4; r++)
        #pragma unroll
        for (int c = 0; c < 4; c++) acc[r][c] = 0ULL;

    const unsigned long long* __restrict__ Wp =
        (const unsigned long long*)Ws;

    for (int kk = 0; kk < K; kk += KC) {
        __syncthreads();
        // load A tile [128 rows][16 k], store transposed+duplicated.
        // 512 slots: r = slot>>2 (0..127), q = slot&3 (float4 along K)
        #pragma unroll
        for (int p = 0; p < 2; p++) {
            int slot = tid + p * 256;
            int r = slot >> 2;
            int q = slot & 3;
            int grow = row0 + r;
            float4 v = make_float4(0.f, 0.f, 0.f, 0.f);
            if (grow < M)
                v = *(const float4*)(A + (size_t)grow * K + kk + q * 4);
            As[(q * 4 + 0) * 128 + r] = dup_f32(v.x);
            As[(q * 4 + 1) * 128 + r] = dup_f32(v.y);
            As[(q * 4 + 2) * 128 + r] = dup_f32(v.z);
            As[(q * 4 + 3) * 128 + r] = dup_f32(v.w);
        }
        __syncthreads();
        #pragma unroll
        for (int k = 0; k < KC; k++) {
            const unsigned long long* ap = As + k * 128 + ty * 4;
            unsigned long long a0 = ap[0], a1 = ap[1], a2 = ap[2], a3 = ap[3];
            const unsigned long long* bp = Wp + (size_t)(kk + k) * 32 + tx * 4;
            unsigned long long b0 = bp[0], b1 = bp[1], b2 = bp[2], b3 = bp[3];
            fma2(acc[0][0], a0, b0); fma2(acc[0][1], a0, b1);
            fma2(acc[0][2], a0, b2); fma2(acc[0][3], a0, b3);
            fma2(acc[1][0], a1, b0); fma2(acc[1][1], a1, b1);
            fma2(acc[1][2], a1, b2); fma2(acc[1][3], a1, b3);
            fma2(acc[2][0], a2, b0); fma2(acc[2][1], a2, b1);
            fma2(acc[2][2], a2, b2); fma2(acc[2][3], a2, b3);
            fma2(acc[3][0], a3, b0); fma2(acc[3][1], a3, b1);
            fma2(acc[3][2], a3, b2); fma2(acc[3][3], a3, b3);
        }
    }

    #pragma unroll
    for (int r = 0; r < 4; r++) {
        int grow = row0 + ty * 4 + r;
        if (grow < M) {
            float2 p0 = *(float2*)&acc[r][0];
            float2 p1 = *(float2*)&acc[r][1];
            float2 p2 = *(float2*)&acc[r][2];
            float2 p3 = *(float2*)&acc[r][3];
            float* cp = C + (size_t)grow * 64 + tx * 8;
            *(float4*)(cp)     = make_float4(p0.x, p0.y, p1.x, p1.y);
            *(float4*)(cp + 4) = make_float4(p2.x, p2.y, p3.x, p3.y);
        }
    }
}

// ---------------- aggregation: g_tmpB[i] = sum_in(g_tmpA[src]*norm)
//                               + g_tmpA[i]/deg + b, optional relu
// one warp per node; lane owns 2 consecutive features (float2)  [round-3 form]
__global__ void aggregate_kernel(const float* __restrict__ bias, int relu) {
    int warp = (blockIdx.x * blockDim.x + threadIdx.x) >> 5;
    if (warp >= N_NODES) return;
    int lane = threadIdx.x & 31;

    const float* __restrict__ hW = g_tmpA;
    float* __restrict__ out = g_tmpB;

    int start = g_rowptr[warp];
    int end   = g_rowptr[warp + 1];
    float d = g_dis[warp];
    float w = d * d;   // self loop weight = 1/deg

    float2 s = *(const float2*)(hW + (size_t)warp * 64 + lane * 2);
    float ax = s.x * w, ay = s.y * w;

    for (int k = start; k < end; k++) {
        int2 p = g_csr_pack[k];
        float nr = __int_as_float(p.y);
        float2 v = *(const float2*)(hW + (size_t)p.x * 64 + lane * 2);
        ax += v.x * nr;
        ay += v.y * nr;
    }

    ax += bias[lane * 2];
    ay += bias[lane * 2 + 1];
    if (relu) { ax = fmaxf(ax, 0.f); ay = fmaxf(ay, 0.f); }
    *(float2*)(out + (size_t)warp * 64 + lane * 2) = make_float2(ax, ay);
}

// ---------------- mean pool over sorted batch ----------------------------
// block = 256 threads = 4 slots x 64 cols; slot handles 128 contiguous nodes
__global__ void pool_kernel(const int* __restrict__ batch) {
    const float* __restrict__ h = g_tmpB;
    int col  = threadIdx.x & 63;
    int slot = threadIdx.x >> 6;
    int n0 = blockIdx.x * 512 + slot * 128;
    if (n0 >= N_NODES) return;
    int n1 = min(n0 + 128, N_NODES);

    float acc = 0.f, cnt = 0.f;
    int cur = batch[n0];
    for (int i = n0; i < n1; i++) {
        int g = batch[i];
        if (g != cur) {
            atomicAdd(&g_pool_sums[cur * 64 + col], acc);
            if (col == 0) atomicAdd(&g_pool_cnt[cur], cnt);
            cur = g; acc = 0.f; cnt = 0.f;
        }
        acc += h[(size_t)i * 64 + col];
        cnt += 1.f;
    }
    atomicAdd(&g_pool_sums[cur * 64 + col], acc);
    if (col == 0) atomicAdd(&g_pool_cnt[cur], cnt);
}

// ---------------- final linear: out = (sums/cnt) @ Wlin + blin ----------
__global__ void final_kernel(const float* __restrict__ Wlin,
                             const float* __restrict__ blin,
                             float* __restrict__ out) {
    int tid = threadIdx.x;
    if (tid >= N_GRAPHS * N_OUT) return;
    int g = tid / N_OUT;
    int o = tid % N_OUT;
    float inv = 1.f / fmaxf(g_pool_cnt[g], 1.f);
    float acc = blin[o];
    #pragma unroll
    for (int c = 0; c < 64; c++)
        acc += g_pool_sums[g * 64 + c] * inv * Wlin[c * N_OUT + o];
    out[g * N_OUT + o] = acc;
}

// ---------------- launch ------------------------------------------------
extern "C" void kernel_launch(void* const* d_in, const int* in_sizes, int n_in,
                              void* d_out, int out_size) {
    const float* x    = (const float*)d_in[0];
    const int*   ei   = (const int*)d_in[1];     // int32 (JAX default x64-disabled)
    const int*   batch= (const int*)d_in[2];     // int32
    const float* W1   = (const float*)d_in[3];
    const float* b1   = (const float*)d_in[4];
    const float* W2   = (const float*)d_in[5];
    const float* b2   = (const float*)d_in[6];
    const float* W3   = (const float*)d_in[7];
    const float* b3   = (const float*)d_in[8];
    const float* Wlin = (const float*)d_in[9];
    const float* blin = (const float*)d_in[10];
    float* out = (float*)d_out;

    const int EBLK = (N_EDGES + 255) / 256;
    const int NBLK = (N_NODES + 255) / 256;

    const int GEMM_BLK = (N_NODES + 127) / 128;
    const int AGG_BLK  = (N_NODES * 32 + 255) / 256;

    // launches 0..2: prep that gemm1 does not depend on CSR for
    init_kernel<<<NBLK, 256>>>();                    // 0
    count_kernel<<<EBLK, 256>>>(ei);                 // 1
    scan1_kernel<<<N_SCAN_BLOCKS, SCAN_B>>>();       // 2

    // launch 3: the big GEMM (x @ W1) — lands in the ncu capture slot
    gemm_kernel<128><<<GEMM_BLK, 256>>>(x, W1, 0, N_NODES);   // 3

    // finish CSR build
    scan3_kernel<<<N_SCAN_BLOCKS, SCAN_B>>>();       // 4
    fill_kernel<<<EBLK, 256>>>(ei);                  // 5

    // layer 1 aggregation
    aggregate_kernel<<<AGG_BLK, 256>>>(b1, 1);
    // layer 2
    gemm_kernel<64><<<GEMM_BLK, 256>>>(x, W2, 1, N_NODES);
    aggregate_kernel<<<AGG_BLK, 256>>>(b2, 1);
    // layer 3
    gemm_kernel<64><<<GEMM_BLK, 256>>>(x, W3, 1, N_NODES);
    aggregate_kernel<<<AGG_BLK, 256>>>(b3, 0);

    // pool + head
    pool_kernel<<<(N_NODES + 511) / 512, 256>>>(batch);
    final_kernel<<<1, N_GRAPHS * N_OUT>>>(Wlin, blin, out);
}

// round 8
// speedup vs baseline: 1.2153x; 1.2153x over previous
#include <cuda_runtime.h>
#include <cuda_bf16.h>
#include <cstdint>

// Problem constants (fixed by the dataset)
#define N_NODES 100000
#define N_EDGES 1600000
#define N_FEAT  128
#define HIDDEN  64
#define N_OUT   10
#define N_GRAPHS 64

#define SCAN_B 1024
#define N_SCAN_BLOCKS ((N_NODES + SCAN_B - 1) / SCAN_B)   // 98

// ---------------- device scratch (static, no allocation) ----------------
__device__ int    g_deg[N_NODES];          // degree incl. self loop
__device__ float  g_dis[N_NODES];          // rsqrt(deg)
__device__ int    g_rowptr[N_NODES + 1];   // CSR offsets (edges only)
__device__ int    g_cursor[N_NODES];       // fill cursors
__device__ int    g_scan_tmp[N_NODES];     // per-block exclusive scan
__device__ int    g_bsum[N_SCAN_BLOCKS];   // per-block totals from scan1
__device__ __align__(16) int2  g_csr_pack[N_EDGES];              // (src, norm-as-bits)
__device__ __align__(16) float g_tmpA[(size_t)N_NODES * HIDDEN]; // h @ W
__device__ __align__(16) float g_tmpB[(size_t)N_NODES * HIDDEN]; // aggregated h
__device__ float  g_pool_sums[N_GRAPHS * HIDDEN];
__device__ float  g_pool_cnt[N_GRAPHS];

// ---------------- init: deg=1 (self loop), zero pool accumulators -------
__global__ void init_kernel() {
    int i = blockIdx.x * blockDim.x + threadIdx.x;
    if (i < N_NODES) g_deg[i] = 1;
    if (i < N_GRAPHS * HIDDEN) g_pool_sums[i] = 0.f;
    if (i < N_GRAPHS) g_pool_cnt[i] = 0.f;
}

// ---------------- degree histogram over targets (col) -------------------
__global__ void count_kernel(const int* __restrict__ ei) {
    int e = blockIdx.x * blockDim.x + threadIdx.x;
    if (e < N_EDGES) {
        int c = ei[e + N_EDGES];   // col / target
        atomicAdd(&g_deg[c], 1);
    }
}

// ---------------- exclusive scan of (deg-1) over 100K nodes + dis -------
__global__ void scan1_kernel() {
    __shared__ int s[SCAN_B];
    int tid = threadIdx.x;
    int i = blockIdx.x * SCAN_B + tid;
    int deg = (i < N_NODES) ? g_deg[i] : 1;
    if (i < N_NODES) g_dis[i] = rsqrtf((float)deg);
    int v = deg - 1;
    s[tid] = v;
    __syncthreads();
    #pragma unroll
    for (int off = 1; off < SCAN_B; off <<= 1) {
        int t = (tid >= off) ? s[tid - off] : 0;
        __syncthreads();
        s[tid] += t;
        __syncthreads();
    }
    if (i < N_NODES) g_scan_tmp[i] = s[tid] - v;   // exclusive
    if (tid == SCAN_B - 1) g_bsum[blockIdx.x] = s[tid];
}

// scan3: each block computes its offset by summing g_bsum[0..blockIdx-1]
__global__ void scan3_kernel() {
    __shared__ int base;
    if (threadIdx.x == 0) {
        int run = 0;
        for (int b = 0; b < blockIdx.x; b++) run += g_bsum[b];
        base = run;
        if (blockIdx.x == 0) g_rowptr[N_NODES] = N_EDGES;
    }
    __syncthreads();
    int i = blockIdx.x * SCAN_B + threadIdx.x;
    if (i < N_NODES) {
        int v = g_scan_tmp[i] + base;
        g_rowptr[i] = v;
        g_cursor[i] = v;
    }
}

// ---------------- CSR fill with precomputed norm -------------------------
__global__ void fill_kernel(const int* __restrict__ ei) {
    int e = blockIdx.x * blockDim.x + threadIdx.x;
    if (e < N_EDGES) {
        int r = ei[e];
        int c = ei[e + N_EDGES];
        int pos = atomicAdd(&g_cursor[c], 1);
        float nr = g_dis[r] * g_dis[c];
        g_csr_pack[pos] = make_int2(r, __float_as_int(nr));
    }
}

// ---------------- SGEMM (scalar FFMA): C[M,64] = A[M,K] @ W[K,64] --------
// A = x (sel==0) or g_tmpB (sel==1).  128x64 block tile, 256 threads.
// Microtile 8 rows x 4 cols:
//   ty = tid>>4 (0..15) -> rows ty*8..ty*8+7   (max 127)
//   tx = tid&15 (0..15) -> cols tx*4..tx*4+3   (max 63)
// Per k-step: 2 LDS.128 (8 a's) + 1 LDS.128 (4 b's) + 32 FFMA.
template <int K>
__global__ __launch_bounds__(256)
void gemm_kernel(const float* __restrict__ x, const float* __restrict__ W,
                 int sel, int M) {
    constexpr int KC = 32;
    __shared__ __align__(16) float Ws[K * 64];      // <=32KB
    __shared__ __align__(16) float As[KC * 128];    // 16KB, As[kloc][row]

    const float* __restrict__ A = (sel == 0) ? x : (const float*)g_tmpB;
    float* __restrict__ C = g_tmpA;

    const int tid = threadIdx.x;
    const int tx = tid & 15;    // cols tx*4 .. tx*4+3
    const int ty = tid >> 4;    // rows ty*8 .. ty*8+7
    const int row0 = blockIdx.x * 128;

    for (int i = tid; i < K * 16; i += 256)
        *(float4*)(Ws + i * 4) = *(const float4*)(W + i * 4);

    float acc[8][4];
    #pragma unroll
    for (int r = 0; r < 8; r++)
        #pragma unroll
        for (int c = 0; c < 4; c++) acc[r][c] = 0.f;

    for (int kk = 0; kk < K; kk += KC) {
        __syncthreads();
        // A tile [128 rows][KC k] -> As[kloc][row], 1024 float4 slots = 4 passes
        #pragma unroll
        for (int p = 0; p < 4; p++) {
            int slot = tid + p * 256;    // 0..1023
            int r = slot >> 3;           // 0..127
            int q = slot & 7;            // 0..7 (float4 along K)
            int grow = row0 + r;
            float4 v = make_float4(0.f, 0.f, 0.f, 0.f);
            if (grow < M)
                v = *(const float4*)(A + (size_t)grow * K + kk + q * 4);
            As[(q * 4 + 0) * 128 + r] = v.x;
            As[(q * 4 + 1) * 128 + r] = v.y;
            As[(q * 4 + 2) * 128 + r] = v.z;
            As[(q * 4 + 3) * 128 + r] = v.w;
        }
        __syncthreads();
        #pragma unroll
        for (int k = 0; k < KC; k++) {
            const float* ap = As + k * 128 + ty * 8;
            float4 alo = *(const float4*)(ap);
            float4 ahi = *(const float4*)(ap + 4);
            float4 b   = *(const float4*)(Ws + (size_t)(kk + k) * 64 + tx * 4);
            float a[8] = {alo.x, alo.y, alo.z, alo.w, ahi.x, ahi.y, ahi.z, ahi.w};
            #pragma unroll
            for (int r = 0; r < 8; r++) {
                acc[r][0] += a[r] * b.x;
                acc[r][1] += a[r] * b.y;
                acc[r][2] += a[r] * b.z;
                acc[r][3] += a[r] * b.w;
            }
        }
    }

    #pragma unroll
    for (int r = 0; r < 8; r++) {
        int grow = row0 + ty * 8 + r;
        if (grow < M)
            *(float4*)(C + (size_t)grow * 64 + tx * 4) =
                make_float4(acc[r][0], acc[r][1], acc[r][2], acc[r][3]);
    }
}

// ---------------- aggregation: g_tmpB[i] = sum_in(g_tmpA[src]*norm)
//                               + g_tmpA[i]/deg + b, optional relu
// one warp per node; lane owns 2 consecutive features (float2)  [round-3 form]
__global__ void aggregate_kernel(const float* __restrict__ bias, int relu) {
    int warp = (blockIdx.x * blockDim.x + threadIdx.x) >> 5;
    if (warp >= N_NODES) return;
    int lane = threadIdx.x & 31;

    const float* __restrict__ hW = g_tmpA;
    float* __restrict__ out = g_tmpB;

    int start = g_rowptr[warp];
    int end   = g_rowptr[warp + 1];
    float d = g_dis[warp];
    float w = d * d;   // self loop weight = 1/deg

    float2 s = *(const float2*)(hW + (size_t)warp * 64 + lane * 2);
    float ax = s.x * w, ay = s.y * w;

    for (int k = start; k < end; k++) {
        int2 p = g_csr_pack[k];
        float nr = __int_as_float(p.y);
        float2 v = *(const float2*)(hW + (size_t)p.x * 64 + lane * 2);
        ax += v.x * nr;
        ay += v.y * nr;
    }

    ax += bias[lane * 2];
    ay += bias[lane * 2 + 1];
    if (relu) { ax = fmaxf(ax, 0.f); ay = fmaxf(ay, 0.f); }
    *(float2*)(out + (size_t)warp * 64 + lane * 2) = make_float2(ax, ay);
}

// ---------------- mean pool over sorted batch ----------------------------
__global__ void pool_kernel(const int* __restrict__ batch) {
    const float* __restrict__ h = g_tmpB;
    int col  = threadIdx.x & 63;
    int slot = threadIdx.x >> 6;
    int n0 = blockIdx.x * 512 + slot * 128;
    if (n0 >= N_NODES) return;
    int n1 = min(n0 + 128, N_NODES);

    float acc = 0.f, cnt = 0.f;
    int cur = batch[n0];
    for (int i = n0; i < n1; i++) {
        int g = batch[i];
        if (g != cur) {
            atomicAdd(&g_pool_sums[cur * 64 + col], acc);
            if (col == 0) atomicAdd(&g_pool_cnt[cur], cnt);
            cur = g; acc = 0.f; cnt = 0.f;
        }
        acc += h[(size_t)i * 64 + col];
        cnt += 1.f;
    }
    atomicAdd(&g_pool_sums[cur * 64 + col], acc);
    if (col == 0) atomicAdd(&g_pool_cnt[cur], cnt);
}

// ---------------- final linear: out = (sums/cnt) @ Wlin + blin ----------
__global__ void final_kernel(const float* __restrict__ Wlin,
                             const float* __restrict__ blin,
                             float* __restrict__ out) {
    int tid = threadIdx.x;
    if (tid >= N_GRAPHS * N_OUT) return;
    int g = tid / N_OUT;
    int o = tid % N_OUT;
    float inv = 1.f / fmaxf(g_pool_cnt[g], 1.f);
    float acc = blin[o];
    #pragma unroll
    for (int c = 0; c < 64; c++)
        acc += g_pool_sums[g * 64 + c] * inv * Wlin[c * N_OUT + o];
    out[g * N_OUT + o] = acc;
}

// ---------------- launch ------------------------------------------------
extern "C" void kernel_launch(void* const* d_in, const int* in_sizes, int n_in,
                              void* d_out, int out_size) {
    const float* x    = (const float*)d_in[0];
    const int*   ei   = (const int*)d_in[1];
    const int*   batch= (const int*)d_in[2];
    const float* W1   = (const float*)d_in[3];
    const float* b1   = (const float*)d_in[4];
    const float* W2   = (const float*)d_in[5];
    const float* b2   = (const float*)d_in[6];
    const float* W3   = (const float*)d_in[7];
    const float* b3   = (const float*)d_in[8];
    const float* Wlin = (const float*)d_in[9];
    const float* blin = (const float*)d_in[10];
    float* out = (float*)d_out;

    const int EBLK = (N_EDGES + 255) / 256;
    const int NBLK = (N_NODES + 255) / 256;

    const int GEMM_BLK = (N_NODES + 127) / 128;
    const int AGG_BLK  = (N_NODES * 32 + 255) / 256;

    // launches 0..2: prep that gemm1 does not depend on
    init_kernel<<<NBLK, 256>>>();                    // 0
    count_kernel<<<EBLK, 256>>>(ei);                 // 1
    scan1_kernel<<<N_SCAN_BLOCKS, SCAN_B>>>();       // 2

    // launch 3: the big GEMM (x @ W1) — ncu capture slot
    gemm_kernel<128><<<GEMM_BLK, 256>>>(x, W1, 0, N_NODES);   // 3

    // finish CSR build
    scan3_kernel<<<N_SCAN_BLOCKS, SCAN_B>>>();       // 4
    fill_kernel<<<EBLK, 256>>>(ei);                  // 5

    // layer 1 aggregation
    aggregate_kernel<<<AGG_BLK, 256>>>(b1, 1);
    // layer 2
    gemm_kernel<64><<<GEMM_BLK, 256>>>(x, W2, 1, N_NODES);
    aggregate_kernel<<<AGG_BLK, 256>>>(b2, 1);
    // layer 3
    gemm_kernel<64><<<GEMM_BLK, 256>>>(x, W3, 1, N_NODES);
    aggregate_kernel<<<AGG_BLK, 256>>>(b3, 0);

    // pool + head
    pool_kernel<<<(N_NODES + 511) / 512, 256>>>(batch);
    final_kernel<<<1, N_GRAPHS * N_OUT>>>(Wlin, blin, out);
}